// round 1
// baseline (speedup 1.0000x reference)
#include <cuda_runtime.h>
#include <math.h>

#define B_ 64
#define S_ 512
#define H_ 1024
#define E_ 768
#define C_ (H_ + E_)
#define NCT 14          // c tiles of 128: 8 (text) + 6 (aspect)

// Scratch: per (batch, c-tile) partial combine-scores, reduced deterministically later.
__device__ float g_part[B_ * NCT * S_];

__device__ __forceinline__ void fma2(unsigned long long &d,
                                     unsigned long long a,
                                     unsigned long long b) {
    // Blackwell packed f32x2 FMA: two fp32 FMAs per instruction.
    asm("fma.rn.f32x2 %0, %1, %2, %0;" : "+l"(d) : "l"(a), "l"(b));
}

// ---------------------------------------------------------------------------
// Kernel 1: fused GEMM + tanh + w_combine reduction.
// score[b,s] = sum_c w_combine[b,c] * tanh( (W X^T)[c,s] )
// Block tile: 128 c-rows x 128 s-cols, K-tile 16. Thread tile 8x8.
// Accumulators are packed f32x2 along the c dimension.
// ---------------------------------------------------------------------------
__global__ __launch_bounds__(256, 2)
void score_kernel(const float* __restrict__ text,
                  const float* __restrict__ aspect,
                  const float* __restrict__ w_text,
                  const float* __restrict__ w_aspect,
                  const float* __restrict__ w_combine)
{
    __shared__ float As[16][128];   // A^T tile: As[k][c]
    __shared__ float Bs[16][256];   // B tile, each s value DUPLICATED: Bs[k][2s]=Bs[k][2s+1]

    const int tx = threadIdx.x & 15;    // s group
    const int ty = threadIdx.x >> 4;    // c group
    const int s0 = blockIdx.x * 128;
    const int ctile = blockIdx.y;
    const int b = blockIdx.z;

    const float* A;
    const float* Bm;
    int K, cg0;
    if (ctile < 8) {
        K = H_;
        cg0 = ctile * 128;
        A  = w_text + (size_t)b * H_ * H_ + (size_t)cg0 * H_;
        Bm = text   + (size_t)b * S_ * H_ + (size_t)s0 * H_;
    } else {
        K = E_;
        const int c0 = (ctile - 8) * 128;
        cg0 = H_ + c0;
        A  = w_aspect + (size_t)b * E_ * E_ + (size_t)c0 * E_;
        Bm = aspect   + (size_t)b * S_ * E_ + (size_t)s0 * E_;
    }

    unsigned long long acc[4][8];       // [c-pair][s], packed f32x2 = 64 fp32 accumulators
    #pragma unroll
    for (int i = 0; i < 4; i++)
        #pragma unroll
        for (int j = 0; j < 8; j++)
            acc[i][j] = 0ull;

    for (int kt = 0; kt < K; kt += 16) {
        // --- load A tile (transposed) and B tile (duplicated) ---
        #pragma unroll
        for (int rep = 0; rep < 2; rep++) {
            const int idx = threadIdx.x + rep * 256;  // 0..511
            const int row = idx >> 2;                 // 0..127
            const int kq  = (idx & 3) << 2;           // 0,4,8,12
            const float4 av = *(const float4*)&A [(size_t)row * K + kt + kq];
            As[kq + 0][row] = av.x;
            As[kq + 1][row] = av.y;
            As[kq + 2][row] = av.z;
            As[kq + 3][row] = av.w;
            const float4 bv = *(const float4*)&Bm[(size_t)row * K + kt + kq];
            *(float2*)&Bs[kq + 0][2 * row] = make_float2(bv.x, bv.x);
            *(float2*)&Bs[kq + 1][2 * row] = make_float2(bv.y, bv.y);
            *(float2*)&Bs[kq + 2][2 * row] = make_float2(bv.z, bv.z);
            *(float2*)&Bs[kq + 3][2 * row] = make_float2(bv.w, bv.w);
        }
        __syncthreads();

        // --- compute ---
        #pragma unroll
        for (int kk = 0; kk < 16; kk++) {
            const ulonglong2 a01 = *(const ulonglong2*)&As[kk][ty * 8];
            const ulonglong2 a23 = *(const ulonglong2*)&As[kk][ty * 8 + 4];
            const ulonglong2 b01 = *(const ulonglong2*)&Bs[kk][tx * 16];
            const ulonglong2 b23 = *(const ulonglong2*)&Bs[kk][tx * 16 + 4];
            const ulonglong2 b45 = *(const ulonglong2*)&Bs[kk][tx * 16 + 8];
            const ulonglong2 b67 = *(const ulonglong2*)&Bs[kk][tx * 16 + 12];
            unsigned long long ap[4] = {a01.x, a01.y, a23.x, a23.y};
            unsigned long long bd[8] = {b01.x, b01.y, b23.x, b23.y,
                                        b45.x, b45.y, b67.x, b67.y};
            #pragma unroll
            for (int i = 0; i < 4; i++)
                #pragma unroll
                for (int j = 0; j < 8; j++)
                    fma2(acc[i][j], ap[i], bd[j]);
        }
        __syncthreads();
    }

    // --- epilogue: tanh, weight by w_combine, reduce over the 128 c-rows ---
    float wc[8];
    const float* wcp = w_combine + (size_t)b * C_ + cg0 + ty * 8;
    #pragma unroll
    for (int i = 0; i < 8; i++) wc[i] = wcp[i];

    float partial[8];
    #pragma unroll
    for (int j = 0; j < 8; j++) partial[j] = 0.f;
    #pragma unroll
    for (int i = 0; i < 4; i++) {
        #pragma unroll
        for (int j = 0; j < 8; j++) {
            const unsigned long long v = acc[i][j];
            const float lo = __uint_as_float((unsigned int)v);
            const float hi = __uint_as_float((unsigned int)(v >> 32));
            partial[j] += tanhf(lo) * wc[2 * i] + tanhf(hi) * wc[2 * i + 1];
        }
    }

    // cross-ty reduction in shared (reuse As: 16*128 floats)
    float* red = &As[0][0];
    #pragma unroll
    for (int j = 0; j < 8; j++) red[ty * 128 + tx * 8 + j] = partial[j];
    __syncthreads();
    #pragma unroll
    for (int st = 8; st > 0; st >>= 1) {
        if (ty < st) {
            #pragma unroll
            for (int j = 0; j < 8; j++)
                red[ty * 128 + tx * 8 + j] += red[(ty + st) * 128 + tx * 8 + j];
        }
        __syncthreads();
    }
    if (ty == 0) {
        #pragma unroll
        for (int j = 0; j < 8; j++)
            g_part[((size_t)b * NCT + ctile) * S_ + s0 + tx * 8 + j] =
                red[tx * 8 + j];
    }
}

// ---------------------------------------------------------------------------
// Kernel 2: reduce c-tile partials + softmax over S. Writes weight to d_out[0:B*S).
// ---------------------------------------------------------------------------
__global__ void softmax_kernel(float* __restrict__ out_w)
{
    __shared__ float sh[S_];
    const int b = blockIdx.x;
    const int t = threadIdx.x;

    float x = 0.f;
    #pragma unroll
    for (int ct = 0; ct < NCT; ct++)
        x += g_part[((size_t)b * NCT + ct) * S_ + t];

    sh[t] = x;
    __syncthreads();
    for (int st = 256; st > 0; st >>= 1) {
        if (t < st) sh[t] = fmaxf(sh[t], sh[t + st]);
        __syncthreads();
    }
    const float mx = sh[0];
    __syncthreads();

    const float e = expf(x - mx);
    sh[t] = e;
    __syncthreads();
    for (int st = 256; st > 0; st >>= 1) {
        if (t < st) sh[t] += sh[t + st];
        __syncthreads();
    }
    out_w[(size_t)b * S_ + t] = e / sh[0];
}

// ---------------------------------------------------------------------------
// Kernel 3: out[b,h] = sum_s text[b,s,h] * weight[b,s]. Writes d_out[B*S : B*S+B*H).
// ---------------------------------------------------------------------------
__global__ __launch_bounds__(256)
void out_kernel(const float* __restrict__ text,
                const float* __restrict__ weight,
                float* __restrict__ outp)
{
    __shared__ float w[S_];
    const int b = blockIdx.y;
    const int h = blockIdx.x * 256 + threadIdx.x;

    for (int i = threadIdx.x; i < S_; i += 256)
        w[i] = weight[(size_t)b * S_ + i];
    __syncthreads();

    const float* tb = text + (size_t)b * S_ * H_ + h;
    float a0 = 0.f, a1 = 0.f, a2 = 0.f, a3 = 0.f;
    #pragma unroll 4
    for (int s = 0; s < S_; s += 4) {
        a0 += tb[(size_t)(s + 0) * H_] * w[s + 0];
        a1 += tb[(size_t)(s + 1) * H_] * w[s + 1];
        a2 += tb[(size_t)(s + 2) * H_] * w[s + 2];
        a3 += tb[(size_t)(s + 3) * H_] * w[s + 3];
    }
    outp[(size_t)b * H_ + h] = (a0 + a1) + (a2 + a3);
}

// ---------------------------------------------------------------------------
extern "C" void kernel_launch(void* const* d_in, const int* in_sizes, int n_in,
                              void* d_out, int out_size)
{
    const float* text      = (const float*)d_in[0];
    const float* aspect    = (const float*)d_in[1];
    const float* w_text    = (const float*)d_in[2];
    const float* w_aspect  = (const float*)d_in[3];
    const float* w_combine = (const float*)d_in[4];
    float* out = (float*)d_out;

    dim3 grid(S_ / 128, NCT, B_);
    score_kernel<<<grid, 256>>>(text, aspect, w_text, w_aspect, w_combine);
    softmax_kernel<<<B_, S_>>>(out);
    out_kernel<<<dim3(H_ / 256, B_), 256>>>(text, out, out + (size_t)B_ * S_);
}